// round 9
// baseline (speedup 1.0000x reference)
#include <cuda_runtime.h>
#include <cstdint>
#include <math.h>

#define BATCH   32
#define NANCH   8732
#define NCLS    81
#define CM1     80
#define TOPK    1000
#define CAP     2048
#define WLCAP   2048
#define NBINS   4096
#define SKIP    2560                  /* histogram only bins < SKIP (score > ~0.056) */
#define MAXOUT  100
#define IMG     300.0f
#define CONF    0.01f
#define LTHR    (-4.6062f)            /* slightly below ln(0.01) */
#define QSCALE  (-889.2336f)          /* 4096 / 4.6062, negated   */
#define BPI     16                    /* histogram blocks per image */

// ---------------- device scratch ----------------
__device__ float    g_boxes[BATCH * NANCH * 4];
__device__ float    g_umax[BATCH * NANCH];    // per-anchor best surrogate
__device__ unsigned g_hist[BATCH * SKIP];

__device__ __forceinline__ int quant(float u) {
    // identical everywhere -> exactly consistent counts/selection
    return (int)(u * QSCALE);
}

// ---------------- decode boxes (+ zero hist, fused) ----------------
__global__ void decode_kernel(const float* __restrict__ pred,
                              const float* __restrict__ priors) {
    int i = blockIdx.x * blockDim.x + threadIdx.x;
    if (i < BATCH * SKIP) g_hist[i] = 0u;

    if (i >= BATCH * NANCH) return;
    int n = i % NANCH;
    float px = priors[n * 4 + 0], py = priors[n * 4 + 1];
    float pw = priors[n * 4 + 2], ph = priors[n * 4 + 3];
    float t0 = pred[i * 4 + 0], t1 = pred[i * 4 + 1];
    float t2 = pred[i * 4 + 2], t3 = pred[i * 4 + 3];
    float cx = t0 * 0.1f * pw + px;
    float cy = t1 * 0.1f * ph + py;
    float w  = expf(t2 * 0.2f) * pw;
    float h  = expf(t3 * 0.2f) * ph;
    g_boxes[i * 4 + 0] = (cx - w * 0.5f) * IMG;
    g_boxes[i * 4 + 1] = (cy - h * 0.5f) * IMG;
    g_boxes[i * 4 + 2] = (cx + w * 0.5f) * IMG;
    g_boxes[i * 4 + 3] = (cy + h * 0.5f) * IMG;
}

// shared softmax core: m via max (order-exact), s via the FIXED xor-reduce
// sequence (order-sensitive — must stay identical in pass0 and final).
struct SoftRes {
    float x0, x1, x2, e0, e1, e2, s, lnS, vmax1, m;
};
__device__ __forceinline__ SoftRes warp_softmax(const float* __restrict__ l, int lane) {
    SoftRes r;
    float v0 = l[lane];
    float v1 = l[lane + 32];
    float v2 = (lane < 17) ? l[lane + 64] : -3.0e38f;

    // max over classes 1..80 (exclude class 0 = lane0's v0)
    float bm = fmaxf(v1, v2);
    if (lane > 0) bm = fmaxf(bm, v0);
#pragma unroll
    for (int o = 16; o; o >>= 1) bm = fmaxf(bm, __shfl_xor_sync(0xffffffffu, bm, o));
    r.vmax1 = bm;
    float vc0 = __shfl_sync(0xffffffffu, v0, 0);
    r.m = fmaxf(bm, vc0);                 // max is exact: same bits as any order

    r.x0 = v0 - r.m; r.x1 = v1 - r.m; r.x2 = v2 - r.m;
    r.e0 = expf(r.x0);
    r.e1 = expf(r.x1);
    r.e2 = (lane < 17) ? expf(r.x2) : 0.0f;
    float s = r.e0 + r.e1 + r.e2;
#pragma unroll
    for (int o = 16; o; o >>= 1) s += __shfl_xor_sync(0xffffffffu, s, o);
    r.s = s;
    r.lnS = logf(s);
    return r;
}

// ---------------- pass 0: softmax stats + sparse smem histogram --------------
__global__ void __launch_bounds__(512) pass0_kernel(const float* __restrict__ logits) {
    __shared__ unsigned sh[SKIP];
    const int b = blockIdx.y;
    const int tid = threadIdx.x;
    const int lane = tid & 31;
    const int warpSlot = blockIdx.x * 16 + (tid >> 5);   // 0..255 within image

    for (int i = tid; i < SKIP; i += 512) sh[i] = 0u;
    __syncthreads();

    for (int n = warpSlot; n < NANCH; n += BPI * 16) {
        const int wg = b * NANCH + n;
        SoftRes r = warp_softmax(logits + (size_t)wg * NCLS, lane);

        float u0 = r.x0 - r.lnS, u1 = r.x1 - r.lnS, u2 = r.x2 - r.lnS;
        if (lane > 0 && u0 > LTHR) { int q = quant(u0); if (q < SKIP) atomicAdd(&sh[q], 1u); }
        if (u1 > LTHR)             { int q = quant(u1); if (q < SKIP) atomicAdd(&sh[q], 1u); }
        if (lane < 17 && u2 > LTHR){ int q = quant(u2); if (q < SKIP) atomicAdd(&sh[q], 1u); }

        if (lane == 0)
            g_umax[wg] = (r.vmax1 - r.m) - r.lnS;   // == max-class u (monotone rounding)
    }
    __syncthreads();

    unsigned* hb = g_hist + (size_t)b * SKIP;
    for (int i = tid; i < SKIP; i += 512) {
        unsigned v = sh[i];
        if (v) atomicAdd(&hb[i], v);
    }
}

// ---------------- final: cutoff + select + rescore + sort + NMS + output -----
// dynamic smem layout:
//   skey  : CAP u64          16384
//   bx1..bs : 6*1024 f32     24576
//   blab,banc : 2*1024 i32    8192
//   wl    : WLCAP i32         8192
//   mat   : TOPK*32 u32     128000
//   keepw,pfxw : 2*32 u32      256
#define SMEM_TOTAL (CAP * 8 + 6 * 1024 * 4 + 2 * 1024 * 4 + WLCAP * 4 + TOPK * 32 * 4 + 2 * 32 * 4)

__global__ void __launch_bounds__(512, 1) final_kernel(const float* __restrict__ logits,
                                                       float* __restrict__ out) {
    extern __shared__ unsigned char smem[];
    unsigned long long* skey = (unsigned long long*)smem;
    float* bx1 = (float*)(smem + CAP * 8);
    float* by1 = bx1 + 1024;
    float* bx2 = by1 + 1024;
    float* by2 = bx2 + 1024;
    float* ba  = by2 + 1024;
    float* bs  = ba  + 1024;
    int* blab  = (int*)(bs + 1024);
    int* banc  = blab + 1024;
    int* wl    = banc + 1024;
    unsigned* mat   = (unsigned*)(wl + WLCAP);
    unsigned* keepw = mat + TOPK * 32;
    unsigned* pfxw  = keepw + 32;

    __shared__ unsigned csumA[512];
    __shared__ unsigned cumaA[512];
    __shared__ unsigned wsumA[16];
    __shared__ unsigned wballA[16];
    __shared__ int s_B, s_wlcnt, s_ccnt, s_done, s_T;

    const int b = blockIdx.x;
    const int tid = threadIdx.x;
    const int warpId = tid >> 5;
    const int lane = tid & 31;

    // ---- Phase A: cutoff bin search (each thread owns 5 bins) ----
    const unsigned* h = g_hist + (size_t)b * SKIP;
    unsigned s5 = 0;
#pragma unroll
    for (int k = 0; k < 5; k++) s5 += h[tid * 5 + k];
    csumA[tid] = s5;
    unsigned x = s5;
#pragma unroll
    for (int o = 1; o < 32; o <<= 1) {
        unsigned y = __shfl_up_sync(0xffffffffu, x, o);
        if (lane >= o) x += y;
    }
    if (lane == 31) wsumA[warpId] = x;
    __syncthreads();

    unsigned off = 0, tot = 0;
#pragma unroll
    for (int i = 0; i < 16; i++) {
        unsigned v = wsumA[i];
        if (i < warpId) off += v;
        tot += v;
    }
    unsigned cum = x + off;
    cumaA[tid] = cum;
    unsigned ball = __ballot_sync(0xffffffffu, cum >= TOPK);
    if (lane == 0) wballA[warpId] = ball;
    __syncthreads();

    if (tid == 0) {
        int B = NBINS - 1;   // fallback: accept all > CONF (unreachable here)
        if (tot >= TOPK) {
            int chunk = 0;
#pragma unroll
            for (int i = 0; i < 16; i++) {
                if (wballA[i]) { chunk = i * 32 + __ffs(wballA[i]) - 1; break; }
            }
            unsigned c = cumaA[chunk] - csumA[chunk];
            B = chunk * 5 + 4;
            for (int k = 0; k < 5; k++) {
                c += h[chunk * 5 + k];
                if (c >= TOPK) { B = chunk * 5 + k; break; }
            }
        }
        s_B = B;
        s_wlcnt = 0;
        s_ccnt = 0;
    }
    for (int i = tid; i < CAP; i += 512) skey[i] = 0ull;
    __syncthreads();

    const int B = s_B;

    // ---- Phase B: coalesced umax scan -> hot-anchor worklist ----
    for (int n = tid; n < NANCH; n += 512) {
        float um = g_umax[(size_t)b * NANCH + n];
        if (um > LTHR && quant(um) <= B) {
            int p = atomicAdd(&s_wlcnt, 1);
            if (p < WLCAP) wl[p] = n;
        }
    }
    __syncthreads();
    int W = s_wlcnt < WLCAP ? s_wlcnt : WLCAP;

    // ---- Phase C: warp-per-hot-anchor exact rescore -> candidate keys ----
    for (int it = warpId; it < W; it += 16) {
        int n = wl[it];
        SoftRes r = warp_softmax(logits + ((size_t)b * NANCH + n) * NCLS, lane);
        float u0 = r.x0 - r.lnS, u1 = r.x1 - r.lnS, u2 = r.x2 - r.lnS;
#pragma unroll
        for (int k = 0; k < 3; k++) {
            int c = lane + k * 32;
            float u = (k == 0) ? u0 : ((k == 1) ? u1 : u2);
            float xx = (k == 0) ? r.x0 : ((k == 1) ? r.x1 : r.x2);
            bool cvalid = (c >= 1) && (c < NCLS);
            if (cvalid && u > LTHR && quant(u) <= B) {
                float e = expf(xx);
                float sc = e / r.s;      // exact same numerics as passing kernel
                if (sc > CONF) {
                    int pos = atomicAdd(&s_ccnt, 1);
                    if (pos < CAP) {
                        unsigned fidx = (unsigned)(n * CM1 + (c - 1));
                        skey[pos] = ((unsigned long long)__float_as_uint(sc) << 32) |
                                    (unsigned long long)(0xFFFFFFFFu - fidx);
                    }
                }
            }
        }
    }
    __syncthreads();

    // ---- bitonic sort descending (2048 keys) ----
    for (int k = 2; k <= CAP; k <<= 1) {
        for (int j = k >> 1; j > 0; j >>= 1) {
            for (int i = tid; i < CAP; i += 512) {
                int ixj = i ^ j;
                if (ixj > i) {
                    unsigned long long a = skey[i], c = skey[ixj];
                    bool desc = ((i & k) == 0);
                    if (desc ? (a < c) : (a > c)) { skey[i] = c; skey[ixj] = a; }
                }
            }
            __syncthreads();
        }
    }

    // ---- extract top TOPK into padded 1024 arrays ----
    for (int i = tid; i < 1024; i += 512) {
        float x1 = 0, y1 = 0, x2 = 0, y2 = 0, sc = -1.0f, area = 0;
        int lab = 0, anc = 0;
        if (i < TOPK) {
            unsigned long long key = skey[i];
            if (key != 0ull) {
                unsigned bits = (unsigned)(key >> 32);
                unsigned fidx = 0xFFFFFFFFu - (unsigned)(key & 0xFFFFFFFFull);
                sc  = __uint_as_float(bits);
                lab = (int)(fidx % CM1) + 1;
                anc = (int)(fidx / CM1);
                const float* bp = g_boxes + ((size_t)b * NANCH + anc) * 4;
                float offc = (float)lab * (2.0f * IMG);
                x1 = bp[0] + offc; y1 = bp[1] + offc;
                x2 = bp[2] + offc; y2 = bp[3] + offc;
                area = (x2 - x1) * (y2 - y1);
            }
        }
        bx1[i] = x1; by1[i] = y1; bx2[i] = x2; by2[i] = y2;
        ba[i] = area; bs[i] = sc; blab[i] = lab; banc[i] = anc;
    }
    __syncthreads();

    // ---- fast path: 256x256 IoU mask ----
    for (int w = warpId; w < 256 * 8; w += 16) {
        int i = w >> 3;
        int jw = w & 7;
        unsigned bits = 0;
        if (jw >= (i >> 5)) {
            int j = jw * 32 + lane;
            float xx1 = fmaxf(bx1[i], bx1[j]);
            float yy1 = fmaxf(by1[i], by1[j]);
            float xx2 = fminf(bx2[i], bx2[j]);
            float yy2 = fminf(by2[i], by2[j]);
            float iw = fmaxf(xx2 - xx1, 0.0f);
            float ih = fmaxf(yy2 - yy1, 0.0f);
            float inter = iw * ih;
            bool o = (1.45f * inter > 0.45f * (ba[i] + ba[j]) + 4.5e-10f);
            bits = __ballot_sync(0xffffffffu, o);
        }
        if (lane == 0) mat[i * 8 + jw] = bits;
    }
    __syncthreads();

    if (tid < 32) {
        unsigned removed = 0, keep = 0;
        int kept = 0;
        for (int i = 0; i < 256; i++) {
            int w = i >> 5;
            unsigned rw = __shfl_sync(0xffffffffu, removed, w);
            bool sup = (rw >> (i & 31)) & 1u;
            bool valid = (!sup) && (bs[i] > 0.0f);
            if (valid) {
                if (lane < 8) removed |= mat[i * 8 + lane];
                if (lane == w) keep |= 1u << (i & 31);
                kept++;
            }
        }
        keepw[lane] = (lane < 8) ? keep : 0u;
        if (lane == 0) { s_done = (kept >= MAXOUT); s_T = kept; }
    }
    __syncthreads();

    // ---- fallback: full 1000x1000 (rare) ----
    if (!s_done) {
        for (int w = warpId; w < TOPK * 32; w += 16) {
            int i = w >> 5;
            int jw = w & 31;
            unsigned bits = 0;
            if (jw >= (i >> 5)) {
                int j = jw * 32 + lane;
                float xx1 = fmaxf(bx1[i], bx1[j]);
                float yy1 = fmaxf(by1[i], by1[j]);
                float xx2 = fminf(bx2[i], bx2[j]);
                float yy2 = fminf(by2[i], by2[j]);
                float iw = fmaxf(xx2 - xx1, 0.0f);
                float ih = fmaxf(yy2 - yy1, 0.0f);
                float inter = iw * ih;
                bool o = (1.45f * inter > 0.45f * (ba[i] + ba[j]) + 4.5e-10f);
                bits = __ballot_sync(0xffffffffu, o);
            }
            if (lane == 0) mat[w] = bits;
        }
        __syncthreads();
        if (tid < 32) {
            unsigned removed = 0, keep = 0;
            int kept = 0;
            for (int i = 0; i < TOPK; i++) {
                int w = i >> 5;
                unsigned rw = __shfl_sync(0xffffffffu, removed, w);
                bool sup = (rw >> (i & 31)) & 1u;
                bool valid = (!sup) && (bs[i] > 0.0f);
                if (valid) {
                    removed |= mat[i * 32 + lane];
                    if (lane == w) keep |= 1u << (i & 31);
                    kept++;
                }
            }
            keepw[lane] = keep;
            if (lane == 0) s_T = kept;
        }
        __syncthreads();
    }

    if (tid < 32) {
        unsigned kw = keepw[lane];
        int p = __popc(kw);
        int xx = p;
#pragma unroll
        for (int o = 1; o < 32; o <<= 1) {
            int y = __shfl_up_sync(0xffffffffu, xx, o);
            if (lane >= o) xx += y;
        }
        pfxw[lane] = xx - p;
        if (lane == 31) s_T = xx;
    }
    __syncthreads();
    int T = s_T;

    for (int i = tid; i < TOPK; i += 512) {
        unsigned kw = keepw[i >> 5];
        if ((kw >> (i & 31)) & 1u) {
            int rank = (int)pfxw[i >> 5] + __popc(kw & ((1u << (i & 31)) - 1u));
            if (rank < MAXOUT) {
                const float* bp = g_boxes + ((size_t)b * NANCH + banc[i]) * 4;
                float* ob = out + (size_t)(b * MAXOUT + rank) * 4;
                ob[0] = bp[0]; ob[1] = bp[1]; ob[2] = bp[2]; ob[3] = bp[3];
                out[BATCH * MAXOUT * 4 + b * MAXOUT + rank] = bs[i];
                out[BATCH * MAXOUT * 5 + b * MAXOUT + rank] = (float)blab[i];
            }
        }
    }
    for (int m = tid; m < MAXOUT; m += 512) {
        if (m >= T) {
            float* ob = out + (size_t)(b * MAXOUT + m) * 4;
            ob[0] = 0; ob[1] = 0; ob[2] = 0; ob[3] = 0;
            out[BATCH * MAXOUT * 4 + b * MAXOUT + m] = 0.0f;
            out[BATCH * MAXOUT * 5 + b * MAXOUT + m] = 0.0f;
        }
    }
}

// ---------------- launch ----------------
extern "C" void kernel_launch(void* const* d_in, const int* in_sizes, int n_in,
                              void* d_out, int out_size) {
    const float* logits = (const float*)d_in[0];
    const float* pred   = (const float*)d_in[1];
    const float* priors = (const float*)d_in[2];
    float* out = (float*)d_out;

    cudaFuncSetAttribute(final_kernel,
                         cudaFuncAttributeMaxDynamicSharedMemorySize, SMEM_TOTAL);

    decode_kernel<<<(BATCH * NANCH + 255) / 256, 256>>>(pred, priors);

    dim3 p0grid(BPI, BATCH);
    pass0_kernel<<<p0grid, 512>>>(logits);

    final_kernel<<<BATCH, 512, SMEM_TOTAL>>>(logits, out);
}

// round 12
// speedup vs baseline: 1.1966x; 1.1966x over previous
#include <cuda_runtime.h>
#include <cstdint>
#include <math.h>

#define BATCH   32
#define NANCH   8732
#define NCLS    81
#define CM1     80
#define TOPK    1000
#define CAP     2048
#define NBINS   4096
#define SKIP    2560                  /* histogram only bins < SKIP (score > ~0.056) */
#define MAXOUT  100
#define IMG     300.0f
#define CONF    0.01f
#define LTHR    (-4.6062f)            /* slightly below ln(0.01) */
#define QSCALE  (-889.2336f)          /* 4096 / 4.6062, negated   */
#define BPI     16                    /* histogram blocks per image */

// ---------------- device scratch ----------------
__device__ float              g_boxes[BATCH * NANCH * 4];
__device__ float              g_umax[BATCH * NANCH];    // per-anchor best surrogate
__device__ unsigned           g_hist[BATCH * SKIP];
__device__ int                g_bcut[BATCH];
__device__ unsigned           g_cnt[BATCH];
__device__ unsigned long long g_cand[BATCH * CAP];

__device__ __forceinline__ int quant(float u) {
    // identical everywhere -> exactly consistent counts/selection
    return (int)(u * QSCALE);
}

// ---------------- decode boxes (+ zero hist/cnt, fused) ----------------
__global__ void decode_kernel(const float* __restrict__ pred,
                              const float* __restrict__ priors) {
    int i = blockIdx.x * blockDim.x + threadIdx.x;
    if (i < BATCH * SKIP) g_hist[i] = 0u;
    if (i < BATCH) g_cnt[i] = 0u;

    if (i >= BATCH * NANCH) return;
    int n = i % NANCH;
    float px = priors[n * 4 + 0], py = priors[n * 4 + 1];
    float pw = priors[n * 4 + 2], ph = priors[n * 4 + 3];
    float t0 = pred[i * 4 + 0], t1 = pred[i * 4 + 1];
    float t2 = pred[i * 4 + 2], t3 = pred[i * 4 + 3];
    float cx = t0 * 0.1f * pw + px;
    float cy = t1 * 0.1f * ph + py;
    float w  = expf(t2 * 0.2f) * pw;
    float h  = expf(t3 * 0.2f) * ph;
    g_boxes[i * 4 + 0] = (cx - w * 0.5f) * IMG;
    g_boxes[i * 4 + 1] = (cy - h * 0.5f) * IMG;
    g_boxes[i * 4 + 2] = (cx + w * 0.5f) * IMG;
    g_boxes[i * 4 + 3] = (cy + h * 0.5f) * IMG;
}

// shared softmax core (validated bit-exact in R9): m via max (order-exact),
// s via the FIXED xor-reduce sequence — identical in pass0 and pass1.
struct SoftRes {
    float x0, x1, x2, e0, e1, e2, s, lnS, vmax1, m;
};
__device__ __forceinline__ SoftRes warp_softmax(const float* __restrict__ l, int lane) {
    SoftRes r;
    float v0 = l[lane];
    float v1 = l[lane + 32];
    float v2 = (lane < 17) ? l[lane + 64] : -3.0e38f;

    // max over classes 1..80 (exclude class 0 = lane0's v0)
    float bm = fmaxf(v1, v2);
    if (lane > 0) bm = fmaxf(bm, v0);
#pragma unroll
    for (int o = 16; o; o >>= 1) bm = fmaxf(bm, __shfl_xor_sync(0xffffffffu, bm, o));
    r.vmax1 = bm;
    float vc0 = __shfl_sync(0xffffffffu, v0, 0);
    r.m = fmaxf(bm, vc0);

    r.x0 = v0 - r.m; r.x1 = v1 - r.m; r.x2 = v2 - r.m;
    r.e0 = expf(r.x0);
    r.e1 = expf(r.x1);
    r.e2 = (lane < 17) ? expf(r.x2) : 0.0f;
    float s = r.e0 + r.e1 + r.e2;
#pragma unroll
    for (int o = 16; o; o >>= 1) s += __shfl_xor_sync(0xffffffffu, s, o);
    r.s = s;
    r.lnS = logf(s);
    return r;
}

// ---------------- pass 0: softmax stats + sparse smem histogram --------------
__global__ void __launch_bounds__(512) pass0_kernel(const float* __restrict__ logits) {
    __shared__ unsigned sh[SKIP];
    const int b = blockIdx.y;
    const int tid = threadIdx.x;
    const int lane = tid & 31;
    const int warpSlot = blockIdx.x * 16 + (tid >> 5);   // 0..255 within image

    for (int i = tid; i < SKIP; i += 512) sh[i] = 0u;
    __syncthreads();

    for (int n = warpSlot; n < NANCH; n += BPI * 16) {
        const int wg = b * NANCH + n;
        SoftRes r = warp_softmax(logits + (size_t)wg * NCLS, lane);

        float u0 = r.x0 - r.lnS, u1 = r.x1 - r.lnS, u2 = r.x2 - r.lnS;
        if (lane > 0 && u0 > LTHR) { int q = quant(u0); if (q < SKIP) atomicAdd(&sh[q], 1u); }
        if (u1 > LTHR)             { int q = quant(u1); if (q < SKIP) atomicAdd(&sh[q], 1u); }
        if (lane < 17 && u2 > LTHR){ int q = quant(u2); if (q < SKIP) atomicAdd(&sh[q], 1u); }

        if (lane == 0)
            g_umax[wg] = (r.vmax1 - r.m) - r.lnS;   // max-class u (R9-validated)
    }
    __syncthreads();

    unsigned* hb = g_hist + (size_t)b * SKIP;
    for (int i = tid; i < SKIP; i += 512) {
        unsigned v = sh[i];
        if (v) atomicAdd(&hb[i], v);
    }
}

// ---------------- cutoff: parallel rank-TOPK bin search ----------------------
__global__ void cutoff_kernel() {
    __shared__ unsigned csum[256];
    __shared__ unsigned cuma[256];
    __shared__ unsigned wsum[8];
    __shared__ unsigned wball[8];
    const int b = blockIdx.x;
    const int t = threadIdx.x;
    const int w = t >> 5, lane = t & 31;
    const unsigned* h = g_hist + (size_t)b * SKIP;
    const int CHW = SKIP / 256;   // 10

    unsigned s = 0;
#pragma unroll
    for (int k = 0; k < CHW; k++) s += h[t * CHW + k];
    csum[t] = s;

    unsigned x = s;
#pragma unroll
    for (int o = 1; o < 32; o <<= 1) {
        unsigned y = __shfl_up_sync(0xffffffffu, x, o);
        if (lane >= o) x += y;
    }
    if (lane == 31) wsum[w] = x;
    __syncthreads();

    unsigned off = 0, tot = 0;
#pragma unroll
    for (int i = 0; i < 8; i++) {
        unsigned v = wsum[i];
        if (i < w) off += v;
        tot += v;
    }
    unsigned cum = x + off;
    cuma[t] = cum;

    if (tot < TOPK) {
        if (t == 0) g_bcut[b] = NBINS - 1;  // accept all > CONF (unreachable here)
        return;
    }

    bool hit = (cum >= TOPK);
    unsigned ball = __ballot_sync(0xffffffffu, hit);
    if (lane == 0) wball[w] = ball;
    __syncthreads();

    if (t == 0) {
        int chunk = 0;
#pragma unroll
        for (int i = 0; i < 8; i++) {
            if (wball[i]) { chunk = i * 32 + __ffs(wball[i]) - 1; break; }
        }
        unsigned c = cuma[chunk] - csum[chunk];
        int B = chunk * CHW + CHW - 1;
        for (int k = 0; k < CHW; k++) {
            c += h[chunk * CHW + k];
            if (c >= TOPK) { B = chunk * CHW + k; break; }
        }
        g_bcut[b] = B;
    }
}

// ---------------- pass 1: filter (thread/anchor) + rescore (warp/hot) --------
// grid (ceil(NANCH/256), BATCH), block 256 = 8 warps.
__global__ void __launch_bounds__(256) pass1_kernel(const float* __restrict__ logits) {
    __shared__ int hot[256];
    __shared__ int hcnt;
    const int b = blockIdx.y;
    const int tid = threadIdx.x;
    const int warpId = tid >> 5;
    const int lane = tid & 31;

    if (tid == 0) hcnt = 0;
    __syncthreads();

    const int B = g_bcut[b];
    int n = blockIdx.x * 256 + tid;
    if (n < NANCH) {
        float um = g_umax[(size_t)b * NANCH + n];   // coalesced
        if (um > LTHR && quant(um) <= B) {
            hot[atomicAdd(&hcnt, 1)] = n;
        }
    }
    __syncthreads();
    const int H = hcnt;

    for (int it = warpId; it < H; it += 8) {
        int nn = hot[it];
        SoftRes r = warp_softmax(logits + ((size_t)b * NANCH + nn) * NCLS, lane);
        float u0 = r.x0 - r.lnS, u1 = r.x1 - r.lnS, u2 = r.x2 - r.lnS;
#pragma unroll
        for (int k = 0; k < 3; k++) {
            int c = lane + k * 32;
            float u = (k == 0) ? u0 : ((k == 1) ? u1 : u2);
            float xx = (k == 0) ? r.x0 : ((k == 1) ? r.x1 : r.x2);
            bool cvalid = (c >= 1) && (c < NCLS);
            if (cvalid && u > LTHR && quant(u) <= B) {
                float e = expf(xx);
                float sc = e / r.s;      // exact same numerics as passing kernels
                if (sc > CONF) {
                    unsigned pos = atomicAdd(&g_cnt[b], 1u);
                    if (pos < CAP) {
                        unsigned fidx = (unsigned)(nn * CM1 + (c - 1));
                        g_cand[b * CAP + pos] =
                            ((unsigned long long)__float_as_uint(sc) << 32) |
                            (unsigned long long)(0xFFFFFFFFu - fidx);
                    }
                }
            }
        }
    }
}

// ---------------- final: sort + NMS + output ----------------
#define SMEM_TOTAL (CAP * 8 + 6 * 1024 * 4 + 2 * 1024 * 4 + TOPK * 32 * 4 + 2 * 32 * 4)

__global__ void __launch_bounds__(512, 1) final_kernel(float* __restrict__ out) {
    extern __shared__ unsigned char smem[];
    unsigned long long* skey = (unsigned long long*)smem;
    float* bx1 = (float*)(smem + CAP * 8);
    float* by1 = bx1 + 1024;
    float* bx2 = by1 + 1024;
    float* by2 = bx2 + 1024;
    float* ba  = by2 + 1024;
    float* bs  = ba  + 1024;
    int* blab  = (int*)(bs + 1024);
    int* banc  = blab + 1024;
    unsigned* mat   = (unsigned*)(banc + 1024);
    unsigned* keepw = mat + TOPK * 32;
    unsigned* pfxw  = keepw + 32;
    __shared__ int s_done;
    __shared__ int s_T;

    const int b = blockIdx.x;
    const int tid = threadIdx.x;

    unsigned cnt = g_cnt[b];
    if (cnt > CAP) cnt = CAP;
    for (int i = tid; i < CAP; i += 512)
        skey[i] = (i < (int)cnt) ? g_cand[b * CAP + i] : 0ull;
    __syncthreads();

    // bitonic sort descending (2048 keys)
    for (int k = 2; k <= CAP; k <<= 1) {
        for (int j = k >> 1; j > 0; j >>= 1) {
            for (int i = tid; i < CAP; i += 512) {
                int ixj = i ^ j;
                if (ixj > i) {
                    unsigned long long a = skey[i], c = skey[ixj];
                    bool desc = ((i & k) == 0);
                    if (desc ? (a < c) : (a > c)) { skey[i] = c; skey[ixj] = a; }
                }
            }
            __syncthreads();
        }
    }

    // extract top TOPK into padded 1024 arrays
    for (int i = tid; i < 1024; i += 512) {
        float x1 = 0, y1 = 0, x2 = 0, y2 = 0, sc = -1.0f, area = 0;
        int lab = 0, anc = 0;
        if (i < TOPK) {
            unsigned long long key = skey[i];
            if (key != 0ull) {
                unsigned bits = (unsigned)(key >> 32);
                unsigned fidx = 0xFFFFFFFFu - (unsigned)(key & 0xFFFFFFFFull);
                sc  = __uint_as_float(bits);
                lab = (int)(fidx % CM1) + 1;
                anc = (int)(fidx / CM1);
                const float* bp = g_boxes + ((size_t)b * NANCH + anc) * 4;
                float off = (float)lab * (2.0f * IMG);
                x1 = bp[0] + off; y1 = bp[1] + off;
                x2 = bp[2] + off; y2 = bp[3] + off;
                area = (x2 - x1) * (y2 - y1);
            }
        }
        bx1[i] = x1; by1[i] = y1; bx2[i] = x2; by2[i] = y2;
        ba[i] = area; bs[i] = sc; blab[i] = lab; banc[i] = anc;
    }
    __syncthreads();

    const int warpId = tid >> 5;
    const int lane = tid & 31;

    // fast path: 256x256 IoU mask
    for (int w = warpId; w < 256 * 8; w += 16) {
        int i = w >> 3;
        int jw = w & 7;
        unsigned bits = 0;
        if (jw >= (i >> 5)) {
            int j = jw * 32 + lane;
            float xx1 = fmaxf(bx1[i], bx1[j]);
            float yy1 = fmaxf(by1[i], by1[j]);
            float xx2 = fminf(bx2[i], bx2[j]);
            float yy2 = fminf(by2[i], by2[j]);
            float iw = fmaxf(xx2 - xx1, 0.0f);
            float ih = fmaxf(yy2 - yy1, 0.0f);
            float inter = iw * ih;
            bool o = (1.45f * inter > 0.45f * (ba[i] + ba[j]) + 4.5e-10f);
            bits = __ballot_sync(0xffffffffu, o);
        }
        if (lane == 0) mat[i * 8 + jw] = bits;
    }
    __syncthreads();

    if (tid < 32) {
        unsigned removed = 0, keep = 0;
        int kept = 0;
        for (int i = 0; i < 256; i++) {
            int w = i >> 5;
            unsigned rw = __shfl_sync(0xffffffffu, removed, w);
            bool sup = (rw >> (i & 31)) & 1u;
            bool valid = (!sup) && (bs[i] > 0.0f);
            if (valid) {
                if (lane < 8) removed |= mat[i * 8 + lane];
                if (lane == w) keep |= 1u << (i & 31);
                kept++;
            }
        }
        keepw[lane] = (lane < 8) ? keep : 0u;
        if (lane == 0) { s_done = (kept >= MAXOUT); s_T = kept; }
    }
    __syncthreads();

    // fallback: full 1000x1000 (rare)
    if (!s_done) {
        for (int w = warpId; w < TOPK * 32; w += 16) {
            int i = w >> 5;
            int jw = w & 31;
            unsigned bits = 0;
            if (jw >= (i >> 5)) {
                int j = jw * 32 + lane;
                float xx1 = fmaxf(bx1[i], bx1[j]);
                float yy1 = fmaxf(by1[i], by1[j]);
                float xx2 = fminf(bx2[i], bx2[j]);
                float yy2 = fminf(by2[i], by2[j]);
                float iw = fmaxf(xx2 - xx1, 0.0f);
                float ih = fmaxf(yy2 - yy1, 0.0f);
                float inter = iw * ih;
                bool o = (1.45f * inter > 0.45f * (ba[i] + ba[j]) + 4.5e-10f);
                bits = __ballot_sync(0xffffffffu, o);
            }
            if (lane == 0) mat[w] = bits;
        }
        __syncthreads();
        if (tid < 32) {
            unsigned removed = 0, keep = 0;
            int kept = 0;
            for (int i = 0; i < TOPK; i++) {
                int w = i >> 5;
                unsigned rw = __shfl_sync(0xffffffffu, removed, w);
                bool sup = (rw >> (i & 31)) & 1u;
                bool valid = (!sup) && (bs[i] > 0.0f);
                if (valid) {
                    removed |= mat[i * 32 + lane];
                    if (lane == w) keep |= 1u << (i & 31);
                    kept++;
                }
            }
            keepw[lane] = keep;
            if (lane == 0) s_T = kept;
        }
        __syncthreads();
    }

    if (tid < 32) {
        unsigned kw = keepw[lane];
        int p = __popc(kw);
        int x = p;
#pragma unroll
        for (int o = 1; o < 32; o <<= 1) {
            int y = __shfl_up_sync(0xffffffffu, x, o);
            if (lane >= o) x += y;
        }
        pfxw[lane] = x - p;
        if (lane == 31) s_T = x;
    }
    __syncthreads();
    int T = s_T;

    for (int i = tid; i < TOPK; i += 512) {
        unsigned kw = keepw[i >> 5];
        if ((kw >> (i & 31)) & 1u) {
            int rank = (int)pfxw[i >> 5] + __popc(kw & ((1u << (i & 31)) - 1u));
            if (rank < MAXOUT) {
                const float* bp = g_boxes + ((size_t)b * NANCH + banc[i]) * 4;
                float* ob = out + (size_t)(b * MAXOUT + rank) * 4;
                ob[0] = bp[0]; ob[1] = bp[1]; ob[2] = bp[2]; ob[3] = bp[3];
                out[BATCH * MAXOUT * 4 + b * MAXOUT + rank] = bs[i];
                out[BATCH * MAXOUT * 5 + b * MAXOUT + rank] = (float)blab[i];
            }
        }
    }
    for (int m = tid; m < MAXOUT; m += 512) {
        if (m >= T) {
            float* ob = out + (size_t)(b * MAXOUT + m) * 4;
            ob[0] = 0; ob[1] = 0; ob[2] = 0; ob[3] = 0;
            out[BATCH * MAXOUT * 4 + b * MAXOUT + m] = 0.0f;
            out[BATCH * MAXOUT * 5 + b * MAXOUT + m] = 0.0f;
        }
    }
}

// ---------------- launch ----------------
extern "C" void kernel_launch(void* const* d_in, const int* in_sizes, int n_in,
                              void* d_out, int out_size) {
    const float* logits = (const float*)d_in[0];
    const float* pred   = (const float*)d_in[1];
    const float* priors = (const float*)d_in[2];
    float* out = (float*)d_out;

    cudaFuncSetAttribute(final_kernel,
                         cudaFuncAttributeMaxDynamicSharedMemorySize, SMEM_TOTAL);

    decode_kernel<<<(BATCH * NANCH + 255) / 256, 256>>>(pred, priors);

    dim3 p0grid(BPI, BATCH);
    pass0_kernel<<<p0grid, 512>>>(logits);
    cutoff_kernel<<<BATCH, 256>>>();

    dim3 p1grid((NANCH + 255) / 256, BATCH);
    pass1_kernel<<<p1grid, 256>>>(logits);

    final_kernel<<<BATCH, 512, SMEM_TOTAL>>>(out);
}

// round 13
// speedup vs baseline: 1.3309x; 1.1122x over previous
#include <cuda_runtime.h>
#include <cstdint>
#include <math.h>

#define BATCH   32
#define NANCH   8732
#define NCLS    81
#define CM1     80
#define TOPK    1000
#define CAP     2048
#define NBINS   4096
#define SKIP    2560                  /* histogram only bins < SKIP (score > ~0.056) */
#define MAXOUT  100
#define IMG     300.0f
#define CONF    0.01f
#define LTHR    (-4.6062f)            /* slightly below ln(0.01) */
#define QSCALE  (-889.2336f)          /* 4096 / 4.6062, negated   */
#define BPI     16                    /* blocks per image in pass0 */
#define APB     546                   /* anchors per pass0 block (16*546 >= 8732) */
#define BUFCAP  1024                  /* pass1 per-block candidate buffer */

// ---------------- device scratch (zero at load; re-zeroed by final_kernel) ---
__device__ float              g_boxes[BATCH * NANCH * 4];
__device__ float              g_umax[BATCH * NANCH];    // per-anchor best surrogate
__device__ unsigned           g_hist[BATCH * SKIP];
__device__ int                g_bcut[BATCH];
__device__ unsigned           g_cnt[BATCH];
__device__ unsigned long long g_cand[BATCH * CAP];

__device__ __forceinline__ int quant(float u) {
    // identical everywhere -> exactly consistent counts/selection
    return (int)(u * QSCALE);
}

// shared softmax core (validated bit-exact): m via max (order-exact), s via the
// FIXED xor-reduce sequence — identical in pass0 and pass1.
struct SoftRes {
    float x0, x1, x2, e0, e1, e2, s, lnS, vmax1, m;
};
__device__ __forceinline__ SoftRes warp_softmax(const float* __restrict__ l, int lane) {
    SoftRes r;
    float v0 = l[lane];
    float v1 = l[lane + 32];
    float v2 = (lane < 17) ? l[lane + 64] : -3.0e38f;

    // max over classes 1..80 (exclude class 0 = lane0's v0)
    float bm = fmaxf(v1, v2);
    if (lane > 0) bm = fmaxf(bm, v0);
#pragma unroll
    for (int o = 16; o; o >>= 1) bm = fmaxf(bm, __shfl_xor_sync(0xffffffffu, bm, o));
    r.vmax1 = bm;
    float vc0 = __shfl_sync(0xffffffffu, v0, 0);
    r.m = fmaxf(bm, vc0);

    r.x0 = v0 - r.m; r.x1 = v1 - r.m; r.x2 = v2 - r.m;
    r.e0 = expf(r.x0);
    r.e1 = expf(r.x1);
    r.e2 = (lane < 17) ? expf(r.x2) : 0.0f;
    float s = r.e0 + r.e1 + r.e2;
#pragma unroll
    for (int o = 16; o; o >>= 1) s += __shfl_xor_sync(0xffffffffu, s, o);
    r.s = s;
    r.lnS = logf(s);
    return r;
}

// ---------------- pass 0: decode (fused) + softmax stats + smem histogram ----
// grid (BPI, BATCH), block 512 = 16 warps.
__global__ void __launch_bounds__(512) pass0_kernel(const float* __restrict__ logits,
                                                    const float* __restrict__ pred,
                                                    const float* __restrict__ priors) {
    __shared__ unsigned sh[SKIP];
    const int b = blockIdx.y;
    const int tid = threadIdx.x;
    const int lane = tid & 31;
    const int warpSlot = blockIdx.x * 16 + (tid >> 5);   // 0..255 within image

    for (int i = tid; i < SKIP; i += 512) sh[i] = 0u;

    // ---- fused decode: this block's anchor slice (independent of hist) ----
    {
        int base_n = blockIdx.x * APB;
        for (int k = tid; k < APB; k += 512) {
            int n = base_n + k;
            if (n < NANCH) {
                int i = b * NANCH + n;
                float px = priors[n * 4 + 0], py = priors[n * 4 + 1];
                float pw = priors[n * 4 + 2], ph = priors[n * 4 + 3];
                float t0 = pred[i * 4 + 0], t1 = pred[i * 4 + 1];
                float t2 = pred[i * 4 + 2], t3 = pred[i * 4 + 3];
                float cx = t0 * 0.1f * pw + px;
                float cy = t1 * 0.1f * ph + py;
                float w  = expf(t2 * 0.2f) * pw;
                float h  = expf(t3 * 0.2f) * ph;
                g_boxes[i * 4 + 0] = (cx - w * 0.5f) * IMG;
                g_boxes[i * 4 + 1] = (cy - h * 0.5f) * IMG;
                g_boxes[i * 4 + 2] = (cx + w * 0.5f) * IMG;
                g_boxes[i * 4 + 3] = (cy + h * 0.5f) * IMG;
            }
        }
    }
    __syncthreads();

    for (int n = warpSlot; n < NANCH; n += BPI * 16) {
        const int wg = b * NANCH + n;
        SoftRes r = warp_softmax(logits + (size_t)wg * NCLS, lane);

        float u0 = r.x0 - r.lnS, u1 = r.x1 - r.lnS, u2 = r.x2 - r.lnS;
        if (lane > 0 && u0 > LTHR) { int q = quant(u0); if (q < SKIP) atomicAdd(&sh[q], 1u); }
        if (u1 > LTHR)             { int q = quant(u1); if (q < SKIP) atomicAdd(&sh[q], 1u); }
        if (lane < 17 && u2 > LTHR){ int q = quant(u2); if (q < SKIP) atomicAdd(&sh[q], 1u); }

        if (lane == 0)
            g_umax[wg] = (r.vmax1 - r.m) - r.lnS;   // max-class u (validated)
    }
    __syncthreads();

    unsigned* hb = g_hist + (size_t)b * SKIP;
    for (int i = tid; i < SKIP; i += 512) {
        unsigned v = sh[i];
        if (v) atomicAdd(&hb[i], v);
    }
}

// ---------------- cutoff: parallel rank-TOPK bin search ----------------------
__global__ void cutoff_kernel() {
    __shared__ unsigned csum[256];
    __shared__ unsigned cuma[256];
    __shared__ unsigned wsum[8];
    __shared__ unsigned wball[8];
    const int b = blockIdx.x;
    const int t = threadIdx.x;
    const int w = t >> 5, lane = t & 31;
    const unsigned* h = g_hist + (size_t)b * SKIP;
    const int CHW = SKIP / 256;   // 10

    unsigned s = 0;
#pragma unroll
    for (int k = 0; k < CHW; k++) s += h[t * CHW + k];
    csum[t] = s;

    unsigned x = s;
#pragma unroll
    for (int o = 1; o < 32; o <<= 1) {
        unsigned y = __shfl_up_sync(0xffffffffu, x, o);
        if (lane >= o) x += y;
    }
    if (lane == 31) wsum[w] = x;
    __syncthreads();

    unsigned off = 0, tot = 0;
#pragma unroll
    for (int i = 0; i < 8; i++) {
        unsigned v = wsum[i];
        if (i < w) off += v;
        tot += v;
    }
    unsigned cum = x + off;
    cuma[t] = cum;

    if (tot < TOPK) {
        if (t == 0) g_bcut[b] = NBINS - 1;  // accept all > CONF (unreachable here)
        return;
    }

    bool hit = (cum >= TOPK);
    unsigned ball = __ballot_sync(0xffffffffu, hit);
    if (lane == 0) wball[w] = ball;
    __syncthreads();

    if (t == 0) {
        int chunk = 0;
#pragma unroll
        for (int i = 0; i < 8; i++) {
            if (wball[i]) { chunk = i * 32 + __ffs(wball[i]) - 1; break; }
        }
        unsigned c = cuma[chunk] - csum[chunk];
        int B = chunk * CHW + CHW - 1;
        for (int k = 0; k < CHW; k++) {
            c += h[chunk * CHW + k];
            if (c >= TOPK) { B = chunk * CHW + k; break; }
        }
        g_bcut[b] = B;
    }
}

// ---------------- pass 1: filter + rescore + BLOCK-AGGREGATED emission -------
// grid (ceil(NANCH/256), BATCH), block 256 = 8 warps.
__global__ void __launch_bounds__(256) pass1_kernel(const float* __restrict__ logits) {
    __shared__ int hot[256];
    __shared__ int hcnt;
    __shared__ int s_ccnt;
    __shared__ unsigned s_base;
    __shared__ unsigned long long cbuf[BUFCAP];
    const int b = blockIdx.y;
    const int tid = threadIdx.x;
    const int warpId = tid >> 5;
    const int lane = tid & 31;

    if (tid == 0) { hcnt = 0; s_ccnt = 0; }
    __syncthreads();

    const int B = g_bcut[b];
    int n = blockIdx.x * 256 + tid;
    if (n < NANCH) {
        float um = g_umax[(size_t)b * NANCH + n];   // coalesced
        if (um > LTHR && quant(um) <= B) {
            hot[atomicAdd(&hcnt, 1)] = n;
        }
    }
    __syncthreads();
    const int H = hcnt;

    for (int it = warpId; it < H; it += 8) {
        int nn = hot[it];
        SoftRes r = warp_softmax(logits + ((size_t)b * NANCH + nn) * NCLS, lane);
        float u0 = r.x0 - r.lnS, u1 = r.x1 - r.lnS, u2 = r.x2 - r.lnS;
#pragma unroll
        for (int k = 0; k < 3; k++) {
            int c = lane + k * 32;
            float u = (k == 0) ? u0 : ((k == 1) ? u1 : u2);
            float xx = (k == 0) ? r.x0 : ((k == 1) ? r.x1 : r.x2);
            bool cvalid = (c >= 1) && (c < NCLS);
            if (cvalid && u > LTHR && quant(u) <= B) {
                float e = expf(xx);
                float sc = e / r.s;      // exact same numerics as passing kernels
                if (sc > CONF) {
                    unsigned fidx = (unsigned)(nn * CM1 + (c - 1));
                    unsigned long long key =
                        ((unsigned long long)__float_as_uint(sc) << 32) |
                        (unsigned long long)(0xFFFFFFFFu - fidx);
                    int pos = atomicAdd(&s_ccnt, 1);
                    if (pos < BUFCAP) {
                        cbuf[pos] = key;
                    } else {             // overflow fallback (never hit in practice)
                        unsigned gp = atomicAdd(&g_cnt[b], 1u);
                        if (gp < CAP) g_cand[b * CAP + gp] = key;
                    }
                }
            }
        }
    }
    __syncthreads();

    int cnt = s_ccnt < BUFCAP ? s_ccnt : BUFCAP;
    if (cnt > 0) {
        if (tid == 0) s_base = atomicAdd(&g_cnt[b], (unsigned)cnt);
        __syncthreads();
        unsigned base = s_base;
        for (int i = tid; i < cnt; i += 256) {
            unsigned p = base + (unsigned)i;
            if (p < CAP) g_cand[b * CAP + p] = cbuf[i];
        }
    }
}

// ---------------- final: sort + NMS + output (+ scratch re-zero) -------------
#define SMEM_TOTAL (CAP * 8 + 6 * 1024 * 4 + 2 * 1024 * 4 + TOPK * 32 * 4 + 2 * 32 * 4)

__global__ void __launch_bounds__(512, 1) final_kernel(float* __restrict__ out) {
    extern __shared__ unsigned char smem[];
    unsigned long long* skey = (unsigned long long*)smem;
    float* bx1 = (float*)(smem + CAP * 8);
    float* by1 = bx1 + 1024;
    float* bx2 = by1 + 1024;
    float* by2 = bx2 + 1024;
    float* ba  = by2 + 1024;
    float* bs  = ba  + 1024;
    int* blab  = (int*)(bs + 1024);
    int* banc  = blab + 1024;
    unsigned* mat   = (unsigned*)(banc + 1024);
    unsigned* keepw = mat + TOPK * 32;
    unsigned* pfxw  = keepw + 32;
    __shared__ int s_done;
    __shared__ int s_T;

    const int b = blockIdx.x;
    const int tid = threadIdx.x;

    unsigned cnt = g_cnt[b];
    if (cnt > CAP) cnt = CAP;
    for (int i = tid; i < CAP; i += 512)
        skey[i] = (i < (int)cnt) ? g_cand[b * CAP + i] : 0ull;
    __syncthreads();

    // bitonic sort descending (2048 keys)
    for (int k = 2; k <= CAP; k <<= 1) {
        for (int j = k >> 1; j > 0; j >>= 1) {
            for (int i = tid; i < CAP; i += 512) {
                int ixj = i ^ j;
                if (ixj > i) {
                    unsigned long long a = skey[i], c = skey[ixj];
                    bool desc = ((i & k) == 0);
                    if (desc ? (a < c) : (a > c)) { skey[i] = c; skey[ixj] = a; }
                }
            }
            __syncthreads();
        }
    }

    // extract top TOPK into padded 1024 arrays
    for (int i = tid; i < 1024; i += 512) {
        float x1 = 0, y1 = 0, x2 = 0, y2 = 0, sc = -1.0f, area = 0;
        int lab = 0, anc = 0;
        if (i < TOPK) {
            unsigned long long key = skey[i];
            if (key != 0ull) {
                unsigned bits = (unsigned)(key >> 32);
                unsigned fidx = 0xFFFFFFFFu - (unsigned)(key & 0xFFFFFFFFull);
                sc  = __uint_as_float(bits);
                lab = (int)(fidx % CM1) + 1;
                anc = (int)(fidx / CM1);
                const float* bp = g_boxes + ((size_t)b * NANCH + anc) * 4;
                float off = (float)lab * (2.0f * IMG);
                x1 = bp[0] + off; y1 = bp[1] + off;
                x2 = bp[2] + off; y2 = bp[3] + off;
                area = (x2 - x1) * (y2 - y1);
            }
        }
        bx1[i] = x1; by1[i] = y1; bx2[i] = x2; by2[i] = y2;
        ba[i] = area; bs[i] = sc; blab[i] = lab; banc[i] = anc;
    }
    __syncthreads();

    const int warpId = tid >> 5;
    const int lane = tid & 31;

    // fast path: 256x256 IoU mask
    for (int w = warpId; w < 256 * 8; w += 16) {
        int i = w >> 3;
        int jw = w & 7;
        unsigned bits = 0;
        if (jw >= (i >> 5)) {
            int j = jw * 32 + lane;
            float xx1 = fmaxf(bx1[i], bx1[j]);
            float yy1 = fmaxf(by1[i], by1[j]);
            float xx2 = fminf(bx2[i], bx2[j]);
            float yy2 = fminf(by2[i], by2[j]);
            float iw = fmaxf(xx2 - xx1, 0.0f);
            float ih = fmaxf(yy2 - yy1, 0.0f);
            float inter = iw * ih;
            bool o = (1.45f * inter > 0.45f * (ba[i] + ba[j]) + 4.5e-10f);
            bits = __ballot_sync(0xffffffffu, o);
        }
        if (lane == 0) mat[i * 8 + jw] = bits;
    }
    __syncthreads();

    if (tid < 32) {
        unsigned removed = 0, keep = 0;
        int kept = 0;
        for (int i = 0; i < 256; i++) {
            int w = i >> 5;
            unsigned rw = __shfl_sync(0xffffffffu, removed, w);
            bool sup = (rw >> (i & 31)) & 1u;
            bool valid = (!sup) && (bs[i] > 0.0f);
            if (valid) {
                if (lane < 8) removed |= mat[i * 8 + lane];
                if (lane == w) keep |= 1u << (i & 31);
                kept++;
            }
        }
        keepw[lane] = (lane < 8) ? keep : 0u;
        if (lane == 0) { s_done = (kept >= MAXOUT); s_T = kept; }
    }
    __syncthreads();

    // fallback: full 1000x1000 (rare)
    if (!s_done) {
        for (int w = warpId; w < TOPK * 32; w += 16) {
            int i = w >> 5;
            int jw = w & 31;
            unsigned bits = 0;
            if (jw >= (i >> 5)) {
                int j = jw * 32 + lane;
                float xx1 = fmaxf(bx1[i], bx1[j]);
                float yy1 = fmaxf(by1[i], by1[j]);
                float xx2 = fminf(bx2[i], bx2[j]);
                float yy2 = fminf(by2[i], by2[j]);
                float iw = fmaxf(xx2 - xx1, 0.0f);
                float ih = fmaxf(yy2 - yy1, 0.0f);
                float inter = iw * ih;
                bool o = (1.45f * inter > 0.45f * (ba[i] + ba[j]) + 4.5e-10f);
                bits = __ballot_sync(0xffffffffu, o);
            }
            if (lane == 0) mat[w] = bits;
        }
        __syncthreads();
        if (tid < 32) {
            unsigned removed = 0, keep = 0;
            int kept = 0;
            for (int i = 0; i < TOPK; i++) {
                int w = i >> 5;
                unsigned rw = __shfl_sync(0xffffffffu, removed, w);
                bool sup = (rw >> (i & 31)) & 1u;
                bool valid = (!sup) && (bs[i] > 0.0f);
                if (valid) {
                    removed |= mat[i * 32 + lane];
                    if (lane == w) keep |= 1u << (i & 31);
                    kept++;
                }
            }
            keepw[lane] = keep;
            if (lane == 0) s_T = kept;
        }
        __syncthreads();
    }

    if (tid < 32) {
        unsigned kw = keepw[lane];
        int p = __popc(kw);
        int x = p;
#pragma unroll
        for (int o = 1; o < 32; o <<= 1) {
            int y = __shfl_up_sync(0xffffffffu, x, o);
            if (lane >= o) x += y;
        }
        pfxw[lane] = x - p;
        if (lane == 31) s_T = x;
    }
    __syncthreads();
    int T = s_T;

    for (int i = tid; i < TOPK; i += 512) {
        unsigned kw = keepw[i >> 5];
        if ((kw >> (i & 31)) & 1u) {
            int rank = (int)pfxw[i >> 5] + __popc(kw & ((1u << (i & 31)) - 1u));
            if (rank < MAXOUT) {
                const float* bp = g_boxes + ((size_t)b * NANCH + banc[i]) * 4;
                float* ob = out + (size_t)(b * MAXOUT + rank) * 4;
                ob[0] = bp[0]; ob[1] = bp[1]; ob[2] = bp[2]; ob[3] = bp[3];
                out[BATCH * MAXOUT * 4 + b * MAXOUT + rank] = bs[i];
                out[BATCH * MAXOUT * 5 + b * MAXOUT + rank] = (float)blab[i];
            }
        }
    }
    for (int m = tid; m < MAXOUT; m += 512) {
        if (m >= T) {
            float* ob = out + (size_t)(b * MAXOUT + m) * 4;
            ob[0] = 0; ob[1] = 0; ob[2] = 0; ob[3] = 0;
            out[BATCH * MAXOUT * 4 + b * MAXOUT + m] = 0.0f;
            out[BATCH * MAXOUT * 5 + b * MAXOUT + m] = 0.0f;
        }
    }

    // ---- self-clean scratch for the next graph replay ----
    if (tid == 0) g_cnt[b] = 0u;
    unsigned* hb = g_hist + (size_t)b * SKIP;
    for (int i = tid; i < SKIP; i += 512) hb[i] = 0u;
}

// ---------------- launch ----------------
extern "C" void kernel_launch(void* const* d_in, const int* in_sizes, int n_in,
                              void* d_out, int out_size) {
    const float* logits = (const float*)d_in[0];
    const float* pred   = (const float*)d_in[1];
    const float* priors = (const float*)d_in[2];
    float* out = (float*)d_out;

    cudaFuncSetAttribute(final_kernel,
                         cudaFuncAttributeMaxDynamicSharedMemorySize, SMEM_TOTAL);

    dim3 p0grid(BPI, BATCH);
    pass0_kernel<<<p0grid, 512>>>(logits, pred, priors);
    cutoff_kernel<<<BATCH, 256>>>();

    dim3 p1grid((NANCH + 255) / 256, BATCH);
    pass1_kernel<<<p1grid, 256>>>(logits);

    final_kernel<<<BATCH, 512, SMEM_TOTAL>>>(out);
}

// round 15
// speedup vs baseline: 1.5253x; 1.1461x over previous
#include <cuda_runtime.h>
#include <cstdint>
#include <math.h>

#define BATCH   32
#define NANCH   8732
#define NCLS    81
#define CM1     80
#define TOPK    1000
#define CAP     2048
#define NBINS   4096
#define SKIP    2560                  /* histogram only bins < SKIP (score > ~0.056) */
#define MAXOUT  100
#define IMG     300.0f
#define CONF    0.01f
#define LTHR    (-4.6062f)            /* slightly below ln(0.01) */
#define QSCALE  (-889.2336f)          /* 4096 / 4.6062, negated   */
#define BPI     16                    /* blocks per image in pass0 */
#define APB     546                   /* anchors per pass0 block (16*546 >= 8732) */
#define BUFCAP  1024                  /* pass1 per-block candidate buffer */
#define FTH     1024                  /* final_kernel threads */

// ---------------- device scratch (zero at load; re-zeroed by final_kernel) ---
__device__ float              g_boxes[BATCH * NANCH * 4];
__device__ float              g_umax[BATCH * NANCH];    // per-anchor best surrogate
__device__ unsigned           g_hist[BATCH * SKIP];
__device__ int                g_bcut[BATCH];
__device__ unsigned           g_cnt[BATCH];
__device__ unsigned long long g_cand[BATCH * CAP];

__device__ __forceinline__ int quant(float u) {
    // identical everywhere -> exactly consistent counts/selection
    return (int)(u * QSCALE);
}

// shared softmax core (validated bit-exact): m via max (order-exact), s via the
// FIXED xor-reduce sequence — identical in pass0 and pass1.
struct SoftRes {
    float x0, x1, x2, e0, e1, e2, s, lnS, vmax1, m;
};
__device__ __forceinline__ SoftRes warp_softmax(const float* __restrict__ l, int lane) {
    SoftRes r;
    float v0 = l[lane];
    float v1 = l[lane + 32];
    float v2 = (lane < 17) ? l[lane + 64] : -3.0e38f;

    // max over classes 1..80 (exclude class 0 = lane0's v0)
    float bm = fmaxf(v1, v2);
    if (lane > 0) bm = fmaxf(bm, v0);
#pragma unroll
    for (int o = 16; o; o >>= 1) bm = fmaxf(bm, __shfl_xor_sync(0xffffffffu, bm, o));
    r.vmax1 = bm;
    float vc0 = __shfl_sync(0xffffffffu, v0, 0);
    r.m = fmaxf(bm, vc0);

    r.x0 = v0 - r.m; r.x1 = v1 - r.m; r.x2 = v2 - r.m;
    r.e0 = expf(r.x0);
    r.e1 = expf(r.x1);
    r.e2 = (lane < 17) ? expf(r.x2) : 0.0f;
    float s = r.e0 + r.e1 + r.e2;
#pragma unroll
    for (int o = 16; o; o >>= 1) s += __shfl_xor_sync(0xffffffffu, s, o);
    r.s = s;
    r.lnS = logf(s);
    return r;
}

// ---------------- pass 0: decode (fused) + softmax stats + smem histogram ----
// grid (BPI, BATCH), block 512 = 16 warps.
__global__ void __launch_bounds__(512) pass0_kernel(const float* __restrict__ logits,
                                                    const float* __restrict__ pred,
                                                    const float* __restrict__ priors) {
    __shared__ unsigned sh[SKIP];
    const int b = blockIdx.y;
    const int tid = threadIdx.x;
    const int lane = tid & 31;
    const int warpSlot = blockIdx.x * 16 + (tid >> 5);   // 0..255 within image

    for (int i = tid; i < SKIP; i += 512) sh[i] = 0u;

    // ---- fused decode: this block's anchor slice (independent of hist) ----
    {
        int base_n = blockIdx.x * APB;
        for (int k = tid; k < APB; k += 512) {
            int n = base_n + k;
            if (n < NANCH) {
                int i = b * NANCH + n;
                float px = priors[n * 4 + 0], py = priors[n * 4 + 1];
                float pw = priors[n * 4 + 2], ph = priors[n * 4 + 3];
                float t0 = pred[i * 4 + 0], t1 = pred[i * 4 + 1];
                float t2 = pred[i * 4 + 2], t3 = pred[i * 4 + 3];
                float cx = t0 * 0.1f * pw + px;
                float cy = t1 * 0.1f * ph + py;
                float w  = expf(t2 * 0.2f) * pw;
                float h  = expf(t3 * 0.2f) * ph;
                g_boxes[i * 4 + 0] = (cx - w * 0.5f) * IMG;
                g_boxes[i * 4 + 1] = (cy - h * 0.5f) * IMG;
                g_boxes[i * 4 + 2] = (cx + w * 0.5f) * IMG;
                g_boxes[i * 4 + 3] = (cy + h * 0.5f) * IMG;
            }
        }
    }
    __syncthreads();

    for (int n = warpSlot; n < NANCH; n += BPI * 16) {
        const int wg = b * NANCH + n;
        SoftRes r = warp_softmax(logits + (size_t)wg * NCLS, lane);

        float u0 = r.x0 - r.lnS, u1 = r.x1 - r.lnS, u2 = r.x2 - r.lnS;
        if (lane > 0 && u0 > LTHR) { int q = quant(u0); if (q < SKIP) atomicAdd(&sh[q], 1u); }
        if (u1 > LTHR)             { int q = quant(u1); if (q < SKIP) atomicAdd(&sh[q], 1u); }
        if (lane < 17 && u2 > LTHR){ int q = quant(u2); if (q < SKIP) atomicAdd(&sh[q], 1u); }

        if (lane == 0)
            g_umax[wg] = (r.vmax1 - r.m) - r.lnS;   // max-class u (validated)
    }
    __syncthreads();

    unsigned* hb = g_hist + (size_t)b * SKIP;
    for (int i = tid; i < SKIP; i += 512) {
        unsigned v = sh[i];
        if (v) atomicAdd(&hb[i], v);
    }
}

// ---------------- cutoff: parallel rank-TOPK bin search ----------------------
__global__ void cutoff_kernel() {
    __shared__ unsigned csum[256];
    __shared__ unsigned cuma[256];
    __shared__ unsigned wsum[8];
    __shared__ unsigned wball[8];
    const int b = blockIdx.x;
    const int t = threadIdx.x;
    const int w = t >> 5, lane = t & 31;
    const unsigned* h = g_hist + (size_t)b * SKIP;
    const int CHW = SKIP / 256;   // 10

    unsigned s = 0;
#pragma unroll
    for (int k = 0; k < CHW; k++) s += h[t * CHW + k];
    csum[t] = s;

    unsigned x = s;
#pragma unroll
    for (int o = 1; o < 32; o <<= 1) {
        unsigned y = __shfl_up_sync(0xffffffffu, x, o);
        if (lane >= o) x += y;
    }
    if (lane == 31) wsum[w] = x;
    __syncthreads();

    unsigned off = 0, tot = 0;
#pragma unroll
    for (int i = 0; i < 8; i++) {
        unsigned v = wsum[i];
        if (i < w) off += v;
        tot += v;
    }
    unsigned cum = x + off;
    cuma[t] = cum;

    if (tot < TOPK) {
        if (t == 0) g_bcut[b] = NBINS - 1;  // accept all > CONF (unreachable here)
        return;
    }

    bool hit = (cum >= TOPK);
    unsigned ball = __ballot_sync(0xffffffffu, hit);
    if (lane == 0) wball[w] = ball;
    __syncthreads();

    if (t == 0) {
        int chunk = 0;
#pragma unroll
        for (int i = 0; i < 8; i++) {
            if (wball[i]) { chunk = i * 32 + __ffs(wball[i]) - 1; break; }
        }
        unsigned c = cuma[chunk] - csum[chunk];
        int B = chunk * CHW + CHW - 1;
        for (int k = 0; k < CHW; k++) {
            c += h[chunk * CHW + k];
            if (c >= TOPK) { B = chunk * CHW + k; break; }
        }
        g_bcut[b] = B;
    }
}

// ---------------- pass 1: filter + rescore + BLOCK-AGGREGATED emission -------
// grid (ceil(NANCH/256), BATCH), block 256 = 8 warps.
__global__ void __launch_bounds__(256) pass1_kernel(const float* __restrict__ logits) {
    __shared__ int hot[256];
    __shared__ int hcnt;
    __shared__ int s_ccnt;
    __shared__ unsigned s_base;
    __shared__ unsigned long long cbuf[BUFCAP];
    const int b = blockIdx.y;
    const int tid = threadIdx.x;
    const int warpId = tid >> 5;
    const int lane = tid & 31;

    if (tid == 0) { hcnt = 0; s_ccnt = 0; }
    __syncthreads();

    const int B = g_bcut[b];
    int n = blockIdx.x * 256 + tid;
    if (n < NANCH) {
        float um = g_umax[(size_t)b * NANCH + n];   // coalesced
        if (um > LTHR && quant(um) <= B) {
            hot[atomicAdd(&hcnt, 1)] = n;
        }
    }
    __syncthreads();
    const int H = hcnt;

    for (int it = warpId; it < H; it += 8) {
        int nn = hot[it];
        SoftRes r = warp_softmax(logits + ((size_t)b * NANCH + nn) * NCLS, lane);
        float u0 = r.x0 - r.lnS, u1 = r.x1 - r.lnS, u2 = r.x2 - r.lnS;
#pragma unroll
        for (int k = 0; k < 3; k++) {
            int c = lane + k * 32;
            float u = (k == 0) ? u0 : ((k == 1) ? u1 : u2);
            float xx = (k == 0) ? r.x0 : ((k == 1) ? r.x1 : r.x2);
            bool cvalid = (c >= 1) && (c < NCLS);
            if (cvalid && u > LTHR && quant(u) <= B) {
                float e = expf(xx);
                float sc = e / r.s;      // exact same numerics as passing kernels
                if (sc > CONF) {
                    unsigned fidx = (unsigned)(nn * CM1 + (c - 1));
                    unsigned long long key =
                        ((unsigned long long)__float_as_uint(sc) << 32) |
                        (unsigned long long)(0xFFFFFFFFu - fidx);
                    int pos = atomicAdd(&s_ccnt, 1);
                    if (pos < BUFCAP) {
                        cbuf[pos] = key;
                    } else {             // overflow fallback (never hit in practice)
                        unsigned gp = atomicAdd(&g_cnt[b], 1u);
                        if (gp < CAP) g_cand[b * CAP + gp] = key;
                    }
                }
            }
        }
    }
    __syncthreads();

    int cnt = s_ccnt < BUFCAP ? s_ccnt : BUFCAP;
    if (cnt > 0) {
        if (tid == 0) s_base = atomicAdd(&g_cnt[b], (unsigned)cnt);
        __syncthreads();
        unsigned base = s_base;
        for (int i = tid; i < cnt; i += 256) {
            unsigned p = base + (unsigned)i;
            if (p < CAP) g_cand[b * CAP + p] = cbuf[i];
        }
    }
}

// ---------------- final: sort + NMS + output (+ scratch re-zero) -------------
// 1024 threads (smem already limits to 1 block/SM, so no occupancy cost).
#define SMEM_TOTAL (CAP * 8 + 6 * 1024 * 4 + 2 * 1024 * 4 + TOPK * 32 * 4 + 2 * 32 * 4)

__global__ void __launch_bounds__(FTH, 1) final_kernel(float* __restrict__ out) {
    extern __shared__ unsigned char smem[];
    unsigned long long* skey = (unsigned long long*)smem;
    float* bx1 = (float*)(smem + CAP * 8);
    float* by1 = bx1 + 1024;
    float* bx2 = by1 + 1024;
    float* by2 = bx2 + 1024;
    float* ba  = by2 + 1024;
    float* bs  = ba  + 1024;
    int* blab  = (int*)(bs + 1024);
    int* banc  = blab + 1024;
    unsigned* mat   = (unsigned*)(banc + 1024);
    unsigned* keepw = mat + TOPK * 32;
    unsigned* pfxw  = keepw + 32;
    __shared__ int s_done;
    __shared__ int s_T;

    const int b = blockIdx.x;
    const int tid = threadIdx.x;

    unsigned cnt = g_cnt[b];
    if (cnt > CAP) cnt = CAP;
    for (int i = tid; i < CAP; i += FTH)
        skey[i] = (i < (int)cnt) ? g_cand[b * CAP + i] : 0ull;
    __syncthreads();

    // bitonic sort descending (2048 keys, 2 elements/thread per round)
    for (int k = 2; k <= CAP; k <<= 1) {
        for (int j = k >> 1; j > 0; j >>= 1) {
            for (int i = tid; i < CAP; i += FTH) {
                int ixj = i ^ j;
                if (ixj > i) {
                    unsigned long long a = skey[i], c = skey[ixj];
                    bool desc = ((i & k) == 0);
                    if (desc ? (a < c) : (a > c)) { skey[i] = c; skey[ixj] = a; }
                }
            }
            __syncthreads();
        }
    }

    // extract top TOPK into padded 1024 arrays
    for (int i = tid; i < 1024; i += FTH) {
        float x1 = 0, y1 = 0, x2 = 0, y2 = 0, sc = -1.0f, area = 0;
        int lab = 0, anc = 0;
        if (i < TOPK) {
            unsigned long long key = skey[i];
            if (key != 0ull) {
                unsigned bits = (unsigned)(key >> 32);
                unsigned fidx = 0xFFFFFFFFu - (unsigned)(key & 0xFFFFFFFFull);
                sc  = __uint_as_float(bits);
                lab = (int)(fidx % CM1) + 1;
                anc = (int)(fidx / CM1);
                const float* bp = g_boxes + ((size_t)b * NANCH + anc) * 4;
                float off = (float)lab * (2.0f * IMG);
                x1 = bp[0] + off; y1 = bp[1] + off;
                x2 = bp[2] + off; y2 = bp[3] + off;
                area = (x2 - x1) * (y2 - y1);
            }
        }
        bx1[i] = x1; by1[i] = y1; bx2[i] = x2; by2[i] = y2;
        ba[i] = area; bs[i] = sc; blab[i] = lab; banc[i] = anc;
    }
    __syncthreads();

    const int warpId = tid >> 5;
    const int lane = tid & 31;

    // fast path: 256x256 IoU mask (32 warps)
    for (int w = warpId; w < 256 * 8; w += FTH / 32) {
        int i = w >> 3;
        int jw = w & 7;
        unsigned bits = 0;
        if (jw >= (i >> 5)) {
            int j = jw * 32 + lane;
            float xx1 = fmaxf(bx1[i], bx1[j]);
            float yy1 = fmaxf(by1[i], by1[j]);
            float xx2 = fminf(bx2[i], bx2[j]);
            float yy2 = fminf(by2[i], by2[j]);
            float iw = fmaxf(xx2 - xx1, 0.0f);
            float ih = fmaxf(yy2 - yy1, 0.0f);
            float inter = iw * ih;
            bool o = (1.45f * inter > 0.45f * (ba[i] + ba[j]) + 4.5e-10f);
            bits = __ballot_sync(0xffffffffu, o);
        }
        if (lane == 0) mat[i * 8 + jw] = bits;
    }
    __syncthreads();

    // sequential greedy scan (warp 0) — early exit once MAXOUT kept:
    // output uses only the first MAXOUT kept candidates, so later
    // suppression decisions are unobservable.
    if (tid < 32) {
        unsigned removed = 0, keep = 0;
        int kept = 0;
        for (int i = 0; i < 256; i++) {
            int w = i >> 5;
            unsigned rw = __shfl_sync(0xffffffffu, removed, w);
            bool sup = (rw >> (i & 31)) & 1u;
            bool valid = (!sup) && (bs[i] > 0.0f);
            if (valid) {
                if (lane < 8) removed |= mat[i * 8 + lane];
                if (lane == w) keep |= 1u << (i & 31);
                kept++;
                if (kept >= MAXOUT) break;
            }
        }
        keepw[lane] = (lane < 8) ? keep : 0u;
        if (lane == 0) { s_done = (kept >= MAXOUT); s_T = kept; }
    }
    __syncthreads();

    // fallback: full 1000x1000 (rare)
    if (!s_done) {
        for (int w = warpId; w < TOPK * 32; w += FTH / 32) {
            int i = w >> 5;
            int jw = w & 31;
            unsigned bits = 0;
            if (jw >= (i >> 5)) {
                int j = jw * 32 + lane;
                float xx1 = fmaxf(bx1[i], bx1[j]);
                float yy1 = fmaxf(by1[i], by1[j]);
                float xx2 = fminf(bx2[i], bx2[j]);
                float yy2 = fminf(by2[i], by2[j]);
                float iw = fmaxf(xx2 - xx1, 0.0f);
                float ih = fmaxf(yy2 - yy1, 0.0f);
                float inter = iw * ih;
                bool o = (1.45f * inter > 0.45f * (ba[i] + ba[j]) + 4.5e-10f);
                bits = __ballot_sync(0xffffffffu, o);
            }
            if (lane == 0) mat[w] = bits;
        }
        __syncthreads();
        if (tid < 32) {
            unsigned removed = 0, keep = 0;
            int kept = 0;
            for (int i = 0; i < TOPK; i++) {
                int w = i >> 5;
                unsigned rw = __shfl_sync(0xffffffffu, removed, w);
                bool sup = (rw >> (i & 31)) & 1u;
                bool valid = (!sup) && (bs[i] > 0.0f);
                if (valid) {
                    removed |= mat[i * 32 + lane];
                    if (lane == w) keep |= 1u << (i & 31);
                    kept++;
                    if (kept >= MAXOUT) break;
                }
            }
            keepw[lane] = keep;
            if (lane == 0) s_T = kept;
        }
        __syncthreads();
    }

    if (tid < 32) {
        unsigned kw = keepw[lane];
        int p = __popc(kw);
        int x = p;
#pragma unroll
        for (int o = 1; o < 32; o <<= 1) {
            int y = __shfl_up_sync(0xffffffffu, x, o);
            if (lane >= o) x += y;
        }
        pfxw[lane] = x - p;
        if (lane == 31) s_T = x;
    }
    __syncthreads();
    int T = s_T;

    for (int i = tid; i < TOPK; i += FTH) {
        unsigned kw = keepw[i >> 5];
        if ((kw >> (i & 31)) & 1u) {
            int rank = (int)pfxw[i >> 5] + __popc(kw & ((1u << (i & 31)) - 1u));
            if (rank < MAXOUT) {
                const float* bp = g_boxes + ((size_t)b * NANCH + banc[i]) * 4;
                float* ob = out + (size_t)(b * MAXOUT + rank) * 4;
                ob[0] = bp[0]; ob[1] = bp[1]; ob[2] = bp[2]; ob[3] = bp[3];
                out[BATCH * MAXOUT * 4 + b * MAXOUT + rank] = bs[i];
                out[BATCH * MAXOUT * 5 + b * MAXOUT + rank] = (float)blab[i];
            }
        }
    }
    for (int m = tid; m < MAXOUT; m += FTH) {
        if (m >= T) {
            float* ob = out + (size_t)(b * MAXOUT + m) * 4;
            ob[0] = 0; ob[1] = 0; ob[2] = 0; ob[3] = 0;
            out[BATCH * MAXOUT * 4 + b * MAXOUT + m] = 0.0f;
            out[BATCH * MAXOUT * 5 + b * MAXOUT + m] = 0.0f;
        }
    }

    // ---- self-clean scratch for the next graph replay ----
    if (tid == 0) g_cnt[b] = 0u;
    unsigned* hb = g_hist + (size_t)b * SKIP;
    for (int i = tid; i < SKIP; i += FTH) hb[i] = 0u;
}

// ---------------- launch ----------------
extern "C" void kernel_launch(void* const* d_in, const int* in_sizes, int n_in,
                              void* d_out, int out_size) {
    const float* logits = (const float*)d_in[0];
    const float* pred   = (const float*)d_in[1];
    const float* priors = (const float*)d_in[2];
    float* out = (float*)d_out;

    cudaFuncSetAttribute(final_kernel,
                         cudaFuncAttributeMaxDynamicSharedMemorySize, SMEM_TOTAL);

    dim3 p0grid(BPI, BATCH);
    pass0_kernel<<<p0grid, 512>>>(logits, pred, priors);
    cutoff_kernel<<<BATCH, 256>>>();

    dim3 p1grid((NANCH + 255) / 256, BATCH);
    pass1_kernel<<<p1grid, 256>>>(logits);

    final_kernel<<<BATCH, FTH, SMEM_TOTAL>>>(out);
}

// round 16
// speedup vs baseline: 1.5861x; 1.0398x over previous
#include <cuda_runtime.h>
#include <cstdint>
#include <math.h>

#define BATCH   32
#define NANCH   8732
#define NCLS    81
#define CM1     80
#define TOPK    1000
#define CAP     2048
#define NBINS   4096
#define SKIP    2560                  /* histogram only bins < SKIP (score > ~0.056) */
#define MAXOUT  100
#define IMG     300.0f
#define CONF    0.01f
#define LTHR    (-4.6062f)            /* slightly below ln(0.01) */
#define QSCALE  (-889.2336f)          /* 4096 / 4.6062, negated   */
#define BPI     16                    /* blocks per image in pass0 */
#define APB     546                   /* anchors per pass0 block (16*546 >= 8732) */
#define BUFCAP  1024                  /* pass1 per-block candidate buffer */
#define FTH     1024                  /* final_kernel threads */

// ---------------- device scratch (zero at load; re-zeroed by final_kernel) ---
__device__ float              g_boxes[BATCH * NANCH * 4];
__device__ float              g_umax[BATCH * NANCH];    // per-anchor best surrogate
__device__ unsigned           g_hist[BATCH * SKIP];
__device__ int                g_bcut[BATCH];
__device__ unsigned           g_cnt[BATCH];
__device__ unsigned long long g_cand[BATCH * CAP];

__device__ __forceinline__ int quant(float u) {
    // identical everywhere -> exactly consistent counts/selection
    return (int)(u * QSCALE);
}

// shared softmax core (validated bit-exact): m via max (order-exact), s via the
// FIXED xor-reduce sequence — identical in pass0 and pass1.
struct SoftRes {
    float x0, x1, x2, e0, e1, e2, s, lnS, vmax1, m;
};
__device__ __forceinline__ SoftRes warp_softmax(const float* __restrict__ l, int lane) {
    SoftRes r;
    float v0 = l[lane];
    float v1 = l[lane + 32];
    float v2 = (lane < 17) ? l[lane + 64] : -3.0e38f;

    // max over classes 1..80 (exclude class 0 = lane0's v0)
    float bm = fmaxf(v1, v2);
    if (lane > 0) bm = fmaxf(bm, v0);
#pragma unroll
    for (int o = 16; o; o >>= 1) bm = fmaxf(bm, __shfl_xor_sync(0xffffffffu, bm, o));
    r.vmax1 = bm;
    float vc0 = __shfl_sync(0xffffffffu, v0, 0);
    r.m = fmaxf(bm, vc0);

    r.x0 = v0 - r.m; r.x1 = v1 - r.m; r.x2 = v2 - r.m;
    r.e0 = expf(r.x0);
    r.e1 = expf(r.x1);
    r.e2 = (lane < 17) ? expf(r.x2) : 0.0f;
    float s = r.e0 + r.e1 + r.e2;
#pragma unroll
    for (int o = 16; o; o >>= 1) s += __shfl_xor_sync(0xffffffffu, s, o);
    r.s = s;
    r.lnS = logf(s);
    return r;
}

// ---------------- pass 0: decode (fused) + softmax stats + smem histogram ----
// grid (BPI, BATCH), block 512 = 16 warps.
__global__ void __launch_bounds__(512) pass0_kernel(const float* __restrict__ logits,
                                                    const float* __restrict__ pred,
                                                    const float* __restrict__ priors) {
    __shared__ unsigned sh[SKIP];
    const int b = blockIdx.y;
    const int tid = threadIdx.x;
    const int lane = tid & 31;
    const int warpSlot = blockIdx.x * 16 + (tid >> 5);   // 0..255 within image

    for (int i = tid; i < SKIP; i += 512) sh[i] = 0u;

    // ---- fused decode: this block's anchor slice (independent of hist) ----
    {
        int base_n = blockIdx.x * APB;
        for (int k = tid; k < APB; k += 512) {
            int n = base_n + k;
            if (n < NANCH) {
                int i = b * NANCH + n;
                float px = priors[n * 4 + 0], py = priors[n * 4 + 1];
                float pw = priors[n * 4 + 2], ph = priors[n * 4 + 3];
                float t0 = pred[i * 4 + 0], t1 = pred[i * 4 + 1];
                float t2 = pred[i * 4 + 2], t3 = pred[i * 4 + 3];
                float cx = t0 * 0.1f * pw + px;
                float cy = t1 * 0.1f * ph + py;
                float w  = expf(t2 * 0.2f) * pw;
                float h  = expf(t3 * 0.2f) * ph;
                g_boxes[i * 4 + 0] = (cx - w * 0.5f) * IMG;
                g_boxes[i * 4 + 1] = (cy - h * 0.5f) * IMG;
                g_boxes[i * 4 + 2] = (cx + w * 0.5f) * IMG;
                g_boxes[i * 4 + 3] = (cy + h * 0.5f) * IMG;
            }
        }
    }
    __syncthreads();

    for (int n = warpSlot; n < NANCH; n += BPI * 16) {
        const int wg = b * NANCH + n;
        SoftRes r = warp_softmax(logits + (size_t)wg * NCLS, lane);

        float u0 = r.x0 - r.lnS, u1 = r.x1 - r.lnS, u2 = r.x2 - r.lnS;
        if (lane > 0 && u0 > LTHR) { int q = quant(u0); if (q < SKIP) atomicAdd(&sh[q], 1u); }
        if (u1 > LTHR)             { int q = quant(u1); if (q < SKIP) atomicAdd(&sh[q], 1u); }
        if (lane < 17 && u2 > LTHR){ int q = quant(u2); if (q < SKIP) atomicAdd(&sh[q], 1u); }

        if (lane == 0)
            g_umax[wg] = (r.vmax1 - r.m) - r.lnS;   // max-class u (validated)
    }
    __syncthreads();

    unsigned* hb = g_hist + (size_t)b * SKIP;
    for (int i = tid; i < SKIP; i += 512) {
        unsigned v = sh[i];
        if (v) atomicAdd(&hb[i], v);
    }
}

// ---------------- cutoff: parallel rank-TOPK bin search ----------------------
__global__ void cutoff_kernel() {
    __shared__ unsigned csum[256];
    __shared__ unsigned cuma[256];
    __shared__ unsigned wsum[8];
    __shared__ unsigned wball[8];
    const int b = blockIdx.x;
    const int t = threadIdx.x;
    const int w = t >> 5, lane = t & 31;
    const unsigned* h = g_hist + (size_t)b * SKIP;
    const int CHW = SKIP / 256;   // 10

    unsigned s = 0;
#pragma unroll
    for (int k = 0; k < CHW; k++) s += h[t * CHW + k];
    csum[t] = s;

    unsigned x = s;
#pragma unroll
    for (int o = 1; o < 32; o <<= 1) {
        unsigned y = __shfl_up_sync(0xffffffffu, x, o);
        if (lane >= o) x += y;
    }
    if (lane == 31) wsum[w] = x;
    __syncthreads();

    unsigned off = 0, tot = 0;
#pragma unroll
    for (int i = 0; i < 8; i++) {
        unsigned v = wsum[i];
        if (i < w) off += v;
        tot += v;
    }
    unsigned cum = x + off;
    cuma[t] = cum;

    if (tot < TOPK) {
        if (t == 0) g_bcut[b] = NBINS - 1;  // accept all > CONF (unreachable here)
        return;
    }

    bool hit = (cum >= TOPK);
    unsigned ball = __ballot_sync(0xffffffffu, hit);
    if (lane == 0) wball[w] = ball;
    __syncthreads();

    if (t == 0) {
        int chunk = 0;
#pragma unroll
        for (int i = 0; i < 8; i++) {
            if (wball[i]) { chunk = i * 32 + __ffs(wball[i]) - 1; break; }
        }
        unsigned c = cuma[chunk] - csum[chunk];
        int B = chunk * CHW + CHW - 1;
        for (int k = 0; k < CHW; k++) {
            c += h[chunk * CHW + k];
            if (c >= TOPK) { B = chunk * CHW + k; break; }
        }
        g_bcut[b] = B;
    }
}

// ---------------- pass 1: filter + rescore + BLOCK-AGGREGATED emission -------
// grid (ceil(NANCH/256), BATCH), block 256 = 8 warps.
__global__ void __launch_bounds__(256) pass1_kernel(const float* __restrict__ logits) {
    __shared__ int hot[256];
    __shared__ int hcnt;
    __shared__ int s_ccnt;
    __shared__ unsigned s_base;
    __shared__ unsigned long long cbuf[BUFCAP];
    const int b = blockIdx.y;
    const int tid = threadIdx.x;
    const int warpId = tid >> 5;
    const int lane = tid & 31;

    if (tid == 0) { hcnt = 0; s_ccnt = 0; }
    __syncthreads();

    const int B = g_bcut[b];
    int n = blockIdx.x * 256 + tid;
    if (n < NANCH) {
        float um = g_umax[(size_t)b * NANCH + n];   // coalesced
        if (um > LTHR && quant(um) <= B) {
            hot[atomicAdd(&hcnt, 1)] = n;
        }
    }
    __syncthreads();
    const int H = hcnt;

    for (int it = warpId; it < H; it += 8) {
        int nn = hot[it];
        SoftRes r = warp_softmax(logits + ((size_t)b * NANCH + nn) * NCLS, lane);
        float u0 = r.x0 - r.lnS, u1 = r.x1 - r.lnS, u2 = r.x2 - r.lnS;
#pragma unroll
        for (int k = 0; k < 3; k++) {
            int c = lane + k * 32;
            float u = (k == 0) ? u0 : ((k == 1) ? u1 : u2);
            float xx = (k == 0) ? r.x0 : ((k == 1) ? r.x1 : r.x2);
            bool cvalid = (c >= 1) && (c < NCLS);
            if (cvalid && u > LTHR && quant(u) <= B) {
                float e = expf(xx);
                float sc = e / r.s;      // exact same numerics as passing kernels
                if (sc > CONF) {
                    unsigned fidx = (unsigned)(nn * CM1 + (c - 1));
                    unsigned long long key =
                        ((unsigned long long)__float_as_uint(sc) << 32) |
                        (unsigned long long)(0xFFFFFFFFu - fidx);
                    int pos = atomicAdd(&s_ccnt, 1);
                    if (pos < BUFCAP) {
                        cbuf[pos] = key;
                    } else {             // overflow fallback (never hit in practice)
                        unsigned gp = atomicAdd(&g_cnt[b], 1u);
                        if (gp < CAP) g_cand[b * CAP + gp] = key;
                    }
                }
            }
        }
    }
    __syncthreads();

    int cnt = s_ccnt < BUFCAP ? s_ccnt : BUFCAP;
    if (cnt > 0) {
        if (tid == 0) s_base = atomicAdd(&g_cnt[b], (unsigned)cnt);
        __syncthreads();
        unsigned base = s_base;
        for (int i = tid; i < cnt; i += 256) {
            unsigned p = base + (unsigned)i;
            if (p < CAP) g_cand[b * CAP + p] = cbuf[i];
        }
    }
}

// ---------------- final: sort + NMS + output (+ scratch re-zero) -------------
// 1024 threads; bitonic sort with warp-local register/shuffle phases for j<=32.
#define SMEM_TOTAL (CAP * 8 + 6 * 1024 * 4 + 2 * 1024 * 4 + TOPK * 32 * 4 + 2 * 32 * 4)

__global__ void __launch_bounds__(FTH, 1) final_kernel(float* __restrict__ out) {
    extern __shared__ unsigned char smem[];
    unsigned long long* skey = (unsigned long long*)smem;
    float* bx1 = (float*)(smem + CAP * 8);
    float* by1 = bx1 + 1024;
    float* bx2 = by1 + 1024;
    float* by2 = bx2 + 1024;
    float* ba  = by2 + 1024;
    float* bs  = ba  + 1024;
    int* blab  = (int*)(bs + 1024);
    int* banc  = blab + 1024;
    unsigned* mat   = (unsigned*)(banc + 1024);
    unsigned* keepw = mat + TOPK * 32;
    unsigned* pfxw  = keepw + 32;
    __shared__ int s_done;
    __shared__ int s_T;

    const int b = blockIdx.x;
    const int tid = threadIdx.x;
    const int warpId = tid >> 5;
    const int lane = tid & 31;

    unsigned cnt = g_cnt[b];
    if (cnt > CAP) cnt = CAP;
    for (int i = tid; i < CAP; i += FTH)
        skey[i] = (i < (int)cnt) ? g_cand[b * CAP + i] : 0ull;
    __syncthreads();

    // ---- bitonic sort descending, 2048 keys ----
    // Keys are unique (distinct flat indices in low bits), so any correct sort
    // yields the identical permutation as the previous smem-only version.
    // Warp w owns elements [64w, 64w+64); lane l holds va=64w+l and vb=va+32.
    // All j<=32 steps are warp-local (register swap at j=32, shfl_xor below).
    {
        const int va = warpId * 64 + lane;
        const int vb = va + 32;
        for (int k = 2; k <= CAP; k <<= 1) {
            // smem phases: j >= 64 (cross-warp)
            for (int j = k >> 1; j >= 64; j >>= 1) {
                for (int i = tid; i < CAP; i += FTH) {
                    int ixj = i ^ j;
                    if (ixj > i) {
                        unsigned long long a = skey[i], c = skey[ixj];
                        bool desc = ((i & k) == 0);
                        if (desc ? (a < c) : (a > c)) { skey[i] = c; skey[ixj] = a; }
                    }
                }
                __syncthreads();
            }
            // warp-local block: j = min(k/2, 32) down to 1
            {
                unsigned long long a = skey[va];
                unsigned long long bkey = skey[vb];
                int j0 = (k >> 1) < 32 ? (k >> 1) : 32;
                if (j0 == 32) {
                    // j=32: both elements in this thread; k>=64 so desc same for both
                    bool desc = ((va & k) == 0);
                    if (desc ? (a < bkey) : (a > bkey)) {
                        unsigned long long t = a; a = bkey; bkey = t;
                    }
                }
                bool descA = ((va & k) == 0);
                bool descB = ((vb & k) == 0);
                for (int j = (j0 >= 32) ? 16 : j0; j >= 1; j >>= 1) {
                    bool lower = ((lane & j) == 0);
                    unsigned long long pa = __shfl_xor_sync(0xffffffffu, a, j);
                    unsigned long long pb = __shfl_xor_sync(0xffffffffu, bkey, j);
                    bool kmA = (descA == lower);
                    bool kmB = (descB == lower);
                    a    = kmA ? (a > pa ? a : pa)       : (a < pa ? a : pa);
                    bkey = kmB ? (bkey > pb ? bkey : pb) : (bkey < pb ? bkey : pb);
                }
                skey[va] = a;
                skey[vb] = bkey;
            }
            __syncthreads();
        }
    }

    // extract top TOPK into padded 1024 arrays
    for (int i = tid; i < 1024; i += FTH) {
        float x1 = 0, y1 = 0, x2 = 0, y2 = 0, sc = -1.0f, area = 0;
        int lab = 0, anc = 0;
        if (i < TOPK) {
            unsigned long long key = skey[i];
            if (key != 0ull) {
                unsigned bits = (unsigned)(key >> 32);
                unsigned fidx = 0xFFFFFFFFu - (unsigned)(key & 0xFFFFFFFFull);
                sc  = __uint_as_float(bits);
                lab = (int)(fidx % CM1) + 1;
                anc = (int)(fidx / CM1);
                const float* bp = g_boxes + ((size_t)b * NANCH + anc) * 4;
                float off = (float)lab * (2.0f * IMG);
                x1 = bp[0] + off; y1 = bp[1] + off;
                x2 = bp[2] + off; y2 = bp[3] + off;
                area = (x2 - x1) * (y2 - y1);
            }
        }
        bx1[i] = x1; by1[i] = y1; bx2[i] = x2; by2[i] = y2;
        ba[i] = area; bs[i] = sc; blab[i] = lab; banc[i] = anc;
    }
    __syncthreads();

    // fast path: 256x256 IoU mask (32 warps)
    for (int w = warpId; w < 256 * 8; w += FTH / 32) {
        int i = w >> 3;
        int jw = w & 7;
        unsigned bits = 0;
        if (jw >= (i >> 5)) {
            int j = jw * 32 + lane;
            float xx1 = fmaxf(bx1[i], bx1[j]);
            float yy1 = fmaxf(by1[i], by1[j]);
            float xx2 = fminf(bx2[i], bx2[j]);
            float yy2 = fminf(by2[i], by2[j]);
            float iw = fmaxf(xx2 - xx1, 0.0f);
            float ih = fmaxf(yy2 - yy1, 0.0f);
            float inter = iw * ih;
            bool o = (1.45f * inter > 0.45f * (ba[i] + ba[j]) + 4.5e-10f);
            bits = __ballot_sync(0xffffffffu, o);
        }
        if (lane == 0) mat[i * 8 + jw] = bits;
    }
    __syncthreads();

    // sequential greedy scan (warp 0) — early exit once MAXOUT kept:
    // output uses only the first MAXOUT kept candidates, so later
    // suppression decisions are unobservable.
    if (tid < 32) {
        unsigned removed = 0, keep = 0;
        int kept = 0;
        for (int i = 0; i < 256; i++) {
            int w = i >> 5;
            unsigned rw = __shfl_sync(0xffffffffu, removed, w);
            bool sup = (rw >> (i & 31)) & 1u;
            bool valid = (!sup) && (bs[i] > 0.0f);
            if (valid) {
                if (lane < 8) removed |= mat[i * 8 + lane];
                if (lane == w) keep |= 1u << (i & 31);
                kept++;
                if (kept >= MAXOUT) break;
            }
        }
        keepw[lane] = (lane < 8) ? keep : 0u;
        if (lane == 0) { s_done = (kept >= MAXOUT); s_T = kept; }
    }
    __syncthreads();

    // fallback: full 1000x1000 (rare)
    if (!s_done) {
        for (int w = warpId; w < TOPK * 32; w += FTH / 32) {
            int i = w >> 5;
            int jw = w & 31;
            unsigned bits = 0;
            if (jw >= (i >> 5)) {
                int j = jw * 32 + lane;
                float xx1 = fmaxf(bx1[i], bx1[j]);
                float yy1 = fmaxf(by1[i], by1[j]);
                float xx2 = fminf(bx2[i], bx2[j]);
                float yy2 = fminf(by2[i], by2[j]);
                float iw = fmaxf(xx2 - xx1, 0.0f);
                float ih = fmaxf(yy2 - yy1, 0.0f);
                float inter = iw * ih;
                bool o = (1.45f * inter > 0.45f * (ba[i] + ba[j]) + 4.5e-10f);
                bits = __ballot_sync(0xffffffffu, o);
            }
            if (lane == 0) mat[w] = bits;
        }
        __syncthreads();
        if (tid < 32) {
            unsigned removed = 0, keep = 0;
            int kept = 0;
            for (int i = 0; i < TOPK; i++) {
                int w = i >> 5;
                unsigned rw = __shfl_sync(0xffffffffu, removed, w);
                bool sup = (rw >> (i & 31)) & 1u;
                bool valid = (!sup) && (bs[i] > 0.0f);
                if (valid) {
                    removed |= mat[i * 32 + lane];
                    if (lane == w) keep |= 1u << (i & 31);
                    kept++;
                    if (kept >= MAXOUT) break;
                }
            }
            keepw[lane] = keep;
            if (lane == 0) s_T = kept;
        }
        __syncthreads();
    }

    if (tid < 32) {
        unsigned kw = keepw[lane];
        int p = __popc(kw);
        int x = p;
#pragma unroll
        for (int o = 1; o < 32; o <<= 1) {
            int y = __shfl_up_sync(0xffffffffu, x, o);
            if (lane >= o) x += y;
        }
        pfxw[lane] = x - p;
        if (lane == 31) s_T = x;
    }
    __syncthreads();
    int T = s_T;

    for (int i = tid; i < TOPK; i += FTH) {
        unsigned kw = keepw[i >> 5];
        if ((kw >> (i & 31)) & 1u) {
            int rank = (int)pfxw[i >> 5] + __popc(kw & ((1u << (i & 31)) - 1u));
            if (rank < MAXOUT) {
                const float* bp = g_boxes + ((size_t)b * NANCH + banc[i]) * 4;
                float* ob = out + (size_t)(b * MAXOUT + rank) * 4;
                ob[0] = bp[0]; ob[1] = bp[1]; ob[2] = bp[2]; ob[3] = bp[3];
                out[BATCH * MAXOUT * 4 + b * MAXOUT + rank] = bs[i];
                out[BATCH * MAXOUT * 5 + b * MAXOUT + rank] = (float)blab[i];
            }
        }
    }
    for (int m = tid; m < MAXOUT; m += FTH) {
        if (m >= T) {
            float* ob = out + (size_t)(b * MAXOUT + m) * 4;
            ob[0] = 0; ob[1] = 0; ob[2] = 0; ob[3] = 0;
            out[BATCH * MAXOUT * 4 + b * MAXOUT + m] = 0.0f;
            out[BATCH * MAXOUT * 5 + b * MAXOUT + m] = 0.0f;
        }
    }

    // ---- self-clean scratch for the next graph replay ----
    if (tid == 0) g_cnt[b] = 0u;
    unsigned* hb = g_hist + (size_t)b * SKIP;
    for (int i = tid; i < SKIP; i += FTH) hb[i] = 0u;
}

// ---------------- launch ----------------
extern "C" void kernel_launch(void* const* d_in, const int* in_sizes, int n_in,
                              void* d_out, int out_size) {
    const float* logits = (const float*)d_in[0];
    const float* pred   = (const float*)d_in[1];
    const float* priors = (const float*)d_in[2];
    float* out = (float*)d_out;

    cudaFuncSetAttribute(final_kernel,
                         cudaFuncAttributeMaxDynamicSharedMemorySize, SMEM_TOTAL);

    dim3 p0grid(BPI, BATCH);
    pass0_kernel<<<p0grid, 512>>>(logits, pred, priors);
    cutoff_kernel<<<BATCH, 256>>>();

    dim3 p1grid((NANCH + 255) / 256, BATCH);
    pass1_kernel<<<p1grid, 256>>>(logits);

    final_kernel<<<BATCH, FTH, SMEM_TOTAL>>>(out);
}